// round 1
// baseline (speedup 1.0000x reference)
#include <cuda_runtime.h>

#define HH 96
#define WW 128
#define CC 21
#define NPIX (HH*WW)   // 12288
#define NITER 5

// ---------------- scratch (no allocations allowed) ----------------
__device__ float g_kprof[128];     // exp(-d^2/18), d = 0..127 (covers both dims)
__device__ float g_rSx[WW];        // 1 / sum_x' exp(-(x-x')^2/18)
__device__ float g_rSy[HH];
__device__ float g_A[CC*CC];       // compat @ (Ws + Wb)
__device__ float g_p [CC*NPIX];    // softmax probs, layout [c][x*96+y]  (y fastest)
__device__ float g_t1[CC*NPIX];    // after y-blur,  layout [c][y*128+x] (x fastest)
__device__ float g_s [CC*NPIX];    // after x-blur + norm, layout [c][x*96+y]

// ---------------- precompute: kernel profile, norms, fused class matrix ----------------
__global__ void precompute_kernel(const float* __restrict__ Ws,
                                  const float* __restrict__ Wb,
                                  const float* __restrict__ Cm) {
    const float inv18 = 1.0f / 18.0f;
    int idx = blockIdx.x * blockDim.x + threadIdx.x;
    int total = 128 + WW + HH + CC*CC;
    for (int i = idx; i < total; i += gridDim.x * blockDim.x) {
        if (i < 128) {
            float d = (float)i;
            g_kprof[i] = expf(-d * d * inv18);
        } else if (i < 128 + WW) {
            int x = i - 128;
            float s = 0.0f;
            for (int xp = 0; xp < WW; xp++) {
                float d = (float)(x - xp);
                s += expf(-d * d * inv18);
            }
            g_rSx[x] = 1.0f / s;
        } else if (i < 128 + WW + HH) {
            int y = i - 128 - WW;
            float s = 0.0f;
            for (int yp = 0; yp < HH; yp++) {
                float d = (float)(y - yp);
                s += expf(-d * d * inv18);
            }
            g_rSy[y] = 1.0f / s;
        } else {
            int a = i - 128 - WW - HH;
            int r = a / CC, c = a % CC;
            float s = 0.0f;
            for (int k = 0; k < CC; k++)
                s += Cm[r*CC + k] * (Ws[k*CC + c] + Wb[k*CC + c]);
            g_A[a] = s;
        }
    }
}

// ---------------- initial softmax: p = softmax(u) ----------------
__global__ void softmax0_kernel(const float* __restrict__ un) {
    int m = blockIdx.x * blockDim.x + threadIdx.x;   // m = x*96 + y
    if (m >= NPIX) return;
    int y = m % HH, x = m / HH;
    const float* ub = un + (y * WW + x) * CC;        // NHWC: contiguous per pixel
    float v[CC];
    float mx = -1e30f;
    #pragma unroll
    for (int c = 0; c < CC; c++) { v[c] = ub[c]; mx = fmaxf(mx, v[c]); }
    float sum = 0.0f;
    #pragma unroll
    for (int c = 0; c < CC; c++) { v[c] = __expf(v[c] - mx); sum += v[c]; }
    float r = 1.0f / sum;
    #pragma unroll
    for (int c = 0; c < CC; c++) g_p[c*NPIX + m] = v[c] * r;
}

// ---------------- y-blur: t1[c][y][x] = sum_y' p[c][x][y'] * kprof(|y'-y|) ----------------
// grid (WW/2, 3), block 192.  Block handles 2 x-columns x 7 classes.
__global__ void blury_kernel() {
    __shared__ float skp[128];
    __shared__ __align__(16) float srows[2 * HH * 8];  // [xs][y'][cc pad 8]
    int t  = threadIdx.x;
    int x0 = blockIdx.x * 2;
    int c0 = blockIdx.y * 7;
    if (t < 128) skp[t] = g_kprof[t];
    for (int i = t; i < 2 * 8 * HH; i += 192) {
        int cc  = i / (2 * HH);
        int pos = i % (2 * HH);
        int xs  = pos / HH;
        int yp  = pos % HH;
        float v = (cc < 7) ? g_p[(c0 + cc)*NPIX + (x0 + xs)*HH + yp] : 0.0f;
        srows[xs*HH*8 + yp*8 + cc] = v;
    }
    __syncthreads();

    int y = t % HH, xs = t / HH;
    float acc[7];
    #pragma unroll
    for (int c = 0; c < 7; c++) acc[c] = 0.0f;

    #pragma unroll 4
    for (int yp = 0; yp < HH; yp++) {
        int d = yp - y; d = (d < 0) ? -d : d;
        float ky = skp[d];
        const float4* rp = (const float4*)&srows[xs*HH*8 + yp*8];
        float4 a = rp[0], b = rp[1];
        acc[0] += a.x * ky; acc[1] += a.y * ky; acc[2] += a.z * ky; acc[3] += a.w * ky;
        acc[4] += b.x * ky; acc[5] += b.y * ky; acc[6] += b.z * ky;
    }
    int base = y * WW + (x0 + xs);
    #pragma unroll
    for (int cc = 0; cc < 7; cc++)
        g_t1[(c0 + cc)*NPIX + base] = acc[cc];
}

// ---------------- x-blur + normalize: s[c][x][y] = (sum_x' t1[c][y][x'] kprof)|*rSx*rSy ----------------
// grid (HH/2, 3), block 256.  Block handles 2 y-rows x 7 classes.
__global__ void blurx_kernel() {
    __shared__ float skp[128];
    __shared__ __align__(16) float srows[2 * WW * 8];  // [ys][x'][cc pad 8]
    int t  = threadIdx.x;
    int y0 = blockIdx.x * 2;
    int c0 = blockIdx.y * 7;
    if (t < 128) skp[t] = g_kprof[t];
    for (int i = t; i < 2 * 8 * WW; i += 256) {
        int cc  = i / (2 * WW);
        int pos = i % (2 * WW);
        int ys  = pos / WW;
        int xp  = pos % WW;
        float v = (cc < 7) ? g_t1[(c0 + cc)*NPIX + (y0 + ys)*WW + xp] : 0.0f;
        srows[ys*WW*8 + xp*8 + cc] = v;
    }
    __syncthreads();

    int x = t % WW, ys = t / WW;
    float acc[7];
    #pragma unroll
    for (int c = 0; c < 7; c++) acc[c] = 0.0f;

    #pragma unroll 4
    for (int xp = 0; xp < WW; xp++) {
        int d = xp - x; d = (d < 0) ? -d : d;
        float kx = skp[d];
        const float4* rp = (const float4*)&srows[ys*WW*8 + xp*8];
        float4 a = rp[0], b = rp[1];
        acc[0] += a.x * kx; acc[1] += a.y * kx; acc[2] += a.z * kx; acc[3] += a.w * kx;
        acc[4] += b.x * kx; acc[5] += b.y * kx; acc[6] += b.z * kx;
    }
    int y = y0 + ys;
    float rn = g_rSx[x] * g_rSy[y];
    int base = x * HH + y;
    #pragma unroll
    for (int cc = 0; cc < 7; cc++)
        g_s[(c0 + cc)*NPIX + base] = acc[cc] * rn;
}

// ---------------- per-pixel update: q = u - A @ s ; then softmax (iters<last) or emit ----------------
__global__ void update_kernel(const float* __restrict__ un,
                              float* __restrict__ out, int last) {
    __shared__ float sA[CC*CC];
    int t = threadIdx.x;
    for (int i = t; i < CC*CC; i += blockDim.x) sA[i] = g_A[i];
    __syncthreads();

    int m = blockIdx.x * blockDim.x + t;     // m = x*96 + y
    if (m >= NPIX) return;
    int y = m % HH, x = m / HH;
    const float* ub = un + (y * WW + x) * CC;

    float sv[CC];
    #pragma unroll
    for (int c = 0; c < CC; c++) sv[c] = g_s[c*NPIX + m];
    float q[CC];
    #pragma unroll
    for (int c = 0; c < CC; c++) q[c] = ub[c];

    for (int cp = 0; cp < CC; cp++) {
        float v = sv[cp];
        #pragma unroll
        for (int c = 0; c < CC; c++) q[c] -= sA[c*CC + cp] * v;
    }

    if (last) {
        float* ob = out + m * CC;            // out[(x*H+y)*C + c] — contiguous
        #pragma unroll
        for (int c = 0; c < CC; c++) ob[c] = q[c];
    } else {
        float mx = q[0];
        #pragma unroll
        for (int c = 1; c < CC; c++) mx = fmaxf(mx, q[c]);
        float sum = 0.0f;
        float e[CC];
        #pragma unroll
        for (int c = 0; c < CC; c++) { e[c] = __expf(q[c] - mx); sum += e[c]; }
        float r = 1.0f / sum;
        #pragma unroll
        for (int c = 0; c < CC; c++) g_p[c*NPIX + m] = e[c] * r;
    }
}

extern "C" void kernel_launch(void* const* d_in, const int* in_sizes, int n_in,
                              void* d_out, int out_size) {
    const float* un = (const float*)d_in[0];
    // d_in[1] = rgb: provably unused (bilateral path is dead in the reference)
    const float* Ws = (const float*)d_in[2];
    const float* Wb = (const float*)d_in[3];
    const float* Cm = (const float*)d_in[4];
    float* out = (float*)d_out;

    precompute_kernel<<<8, 128>>>(Ws, Wb, Cm);
    softmax0_kernel<<<NPIX / 128, 128>>>(un);
    for (int it = 0; it < NITER; it++) {
        blury_kernel<<<dim3(WW / 2, 3), 192>>>();
        blurx_kernel<<<dim3(HH / 2, 3), 256>>>();
        update_kernel<<<NPIX / 128, 128>>>(un, out, (it == NITER - 1) ? 1 : 0);
    }
}

// round 2
// speedup vs baseline: 1.5954x; 1.5954x over previous
#include <cuda_runtime.h>

#define HH 96
#define WW 128
#define CC 21
#define NPIX (HH*WW)   // 12288
#define NITER 5

// ---------------- scratch (no allocations allowed) ----------------
__device__ float g_kx2[256];     // kprof(|j-127|), j=0..254 (+pad)
__device__ float g_ky2[192];     // kprof(|j-95|),  j=0..191
__device__ float g_rSx[WW];      // 1 / sum_x' kprof(|x-x'|)
__device__ float g_rSy[HH];
__device__ float g_A[CC*CC];     // compat @ (Ws + Wb)
__device__ float g_ut[CC*NPIX];  // unaries transposed  [c][x*96+y]
__device__ float g_p [CC*NPIX];  // probs               [c][x*96+y]
__device__ float g_t1[CC*NPIX];  // after y-blur        [c][y*128+x]
__device__ float g_s [CC*NPIX];  // after x-blur+norm   [c][x*96+y]

// ---------------- init: softmax0 + u-transpose + precompute (one launch) ----------------
// grid 56 x 256: blocks 0..47 -> softmax over 12288 pixels; blocks 48..55 -> tables.
__global__ void init_kernel(const float* __restrict__ un,
                            const float* __restrict__ Ws,
                            const float* __restrict__ Wb,
                            const float* __restrict__ Cm) {
    const float inv18 = 1.0f / 18.0f;
    if (blockIdx.x < 48) {
        int m = blockIdx.x * 256 + threadIdx.x;     // m = x*96 + y
        int y = m % HH, x = m / HH;
        const float* ub = un + (y * WW + x) * CC;   // NHWC pixel
        float v[CC];
        float mx = -1e30f;
        #pragma unroll
        for (int c = 0; c < CC; c++) { v[c] = ub[c]; mx = fmaxf(mx, v[c]); }
        float sum = 0.0f;
        #pragma unroll
        for (int c = 0; c < CC; c++) {
            g_ut[c*NPIX + m] = v[c];                // transposed copy of u
            v[c] = __expf(v[c] - mx); sum += v[c];
        }
        float r = 1.0f / sum;
        #pragma unroll
        for (int c = 0; c < CC; c++) g_p[c*NPIX + m] = v[c] * r;
    } else {
        int idx = (blockIdx.x - 48) * 256 + threadIdx.x;
        int total = 255 + 192 + WW + HH + CC*CC;    // 1112
        for (int i = idx; i < total; i += 8 * 256) {
            if (i < 255) {
                float d = (float)(i - 127); d = fabsf(d);
                g_kx2[i] = expf(-d * d * inv18);
            } else if (i < 255 + 192) {
                int j = i - 255;
                float d = fabsf((float)(j - 95));
                g_ky2[j] = expf(-d * d * inv18);
            } else if (i < 255 + 192 + WW) {
                int x = i - (255 + 192);
                float s = 0.0f;
                for (int xp = 0; xp < WW; xp++) {
                    float d = (float)(x - xp);
                    s += expf(-d * d * inv18);
                }
                g_rSx[x] = 1.0f / s;
            } else if (i < 255 + 192 + WW + HH) {
                int y = i - (255 + 192 + WW);
                float s = 0.0f;
                for (int yp = 0; yp < HH; yp++) {
                    float d = (float)(y - yp);
                    s += expf(-d * d * inv18);
                }
                g_rSy[y] = 1.0f / s;
            } else {
                int a = i - (255 + 192 + WW + HH);
                int r = a / CC, c = a % CC;
                float s = 0.0f;
                for (int k = 0; k < CC; k++)
                    s += Cm[r*CC + k] * (Ws[k*CC + c] + Wb[k*CC + c]);
                g_A[a] = s;
            }
        }
    }
}

// ---------------- y-blur: t1[c][y][x] = sum_yp p[c][x][yp] * ky(|yp-y|) ----------------
// grid (8, 21), block 256 = 16 x-columns x 16 thread-rows; thread computes 6 y outputs.
__global__ void blury_kernel() {
    __shared__ float sky[192];
    __shared__ float sp[16 * 97];                   // [col][y] pad 97
    int tid = threadIdx.x;
    int c  = blockIdx.y;
    int x0 = blockIdx.x * 16;
    if (tid < 192) sky[tid] = g_ky2[tid];
    const float* pc = g_p + c*NPIX + x0*96;
    #pragma unroll
    for (int i = tid; i < 16 * 24; i += 256) {      // 16 cols x 24 float4
        int col = i / 24, j = i % 24;
        float4 v = *(const float4*)(pc + col*96 + j*4);
        float* d = &sp[col*97 + j*4];
        d[0] = v.x; d[1] = v.y; d[2] = v.z; d[3] = v.w;
    }
    __syncthreads();

    int lx = tid & 15, ty = tid >> 4;
    int y0 = ty * 6;
    const float* spv  = &sp[lx * 97];
    const float* skyb = &sky[95 - y0];              // weight(yp,k) = skyb[yp - k]
    float acc[6] = {0.f, 0.f, 0.f, 0.f, 0.f, 0.f};
    float w[6];
    #pragma unroll
    for (int k = 0; k < 6; k++) w[k] = skyb[-k];    // yp = 0
    #pragma unroll
    for (int yp = 0; yp < 96; yp++) {
        float v = spv[yp];
        #pragma unroll
        for (int k = 0; k < 6; k++) acc[k] += v * w[k];
        #pragma unroll
        for (int k = 5; k > 0; k--) w[k] = w[k-1];  // slide weight window
        w[0] = skyb[yp + 1];                        // max idx 191 (dead at yp=95)
    }
    float* tb = g_t1 + c*NPIX + y0*128 + x0 + lx;
    #pragma unroll
    for (int k = 0; k < 6; k++) tb[k * 128] = acc[k];
}

// ---------------- x-blur + normalize: s[c][x][y] = (sum_xp t1[c][y][xp] kx)*rSx*rSy ----------------
// grid (6, 21), block 256 = 16 y-rows x 16 x-tiles; thread computes 8 x outputs.
__global__ void blurx_kernel() {
    __shared__ float st[16 * 129];                  // [row][x] pad 129
    __shared__ float sw[16 * 137];                  // per-x-tile weight replicas
    __shared__ float ss[128 * 17];                  // staged transpose [x][row]
    int tid = threadIdx.x;
    int c   = blockIdx.y;
    int y0b = blockIdx.x * 16;

    const float* tc = g_t1 + c*NPIX + y0b*128;
    #pragma unroll
    for (int i = tid; i < 16 * 32; i += 256) {      // 16 rows x 32 float4
        int r = i >> 5, j = i & 31;
        float4 v = *(const float4*)(tc + r*128 + j*4);
        float* d = &st[r*129 + j*4];
        d[0] = v.x; d[1] = v.y; d[2] = v.z; d[3] = v.w;
    }
    for (int i = tid; i < 16 * 137; i += 256) {     // sw[xt][m] = kx2[m + 120 - 8*xt]
        int xt = i / 137, m = i % 137;
        int idx = m + 120 - 8 * xt;
        sw[i] = g_kx2[idx > 254 ? 254 : idx];
    }
    __syncthreads();

    int xt = tid & 15, r = tid >> 4;
    const float* stv = &st[r * 129];
    const float* swt = &sw[xt * 137];               // weight(xp,k) = swt[xp + 7 - k]
    float acc[8] = {0.f,0.f,0.f,0.f,0.f,0.f,0.f,0.f};
    float w[8];
    #pragma unroll
    for (int k = 0; k < 8; k++) w[k] = swt[7 - k];  // xp = 0
    #pragma unroll
    for (int xp = 0; xp < 128; xp++) {
        float v = stv[xp];
        #pragma unroll
        for (int k = 0; k < 8; k++) acc[k] += v * w[k];
        #pragma unroll
        for (int k = 7; k > 0; k--) w[k] = w[k-1];
        w[0] = swt[xp + 8];                         // m<=135 (dead at xp=127)
    }

    int x0 = xt * 8;
    float rn_y = g_rSy[y0b + r];
    #pragma unroll
    for (int k = 0; k < 8; k++)
        ss[(x0 + k) * 17 + r] = acc[k] * g_rSx[x0 + k] * rn_y;
    __syncthreads();

    float* sb = g_s + c*NPIX + y0b;                 // coalesced float4 writeback
    #pragma unroll
    for (int i = tid; i < 512; i += 256) {
        int x = i >> 2, q = i & 3;
        const float* p4 = &ss[x * 17 + q * 4];
        float4 v = make_float4(p4[0], p4[1], p4[2], p4[3]);
        *(float4*)(sb + x*96 + q*4) = v;
    }
}

// ---------------- per-pixel: q = u - A @ s ; softmax (or emit on last iter) ----------------
__global__ void update_kernel(float* __restrict__ out, int last) {
    __shared__ float sA[CC * CC];
    int t = threadIdx.x;
    for (int i = t; i < CC*CC; i += 128) sA[i] = g_A[i];
    __syncthreads();

    int m = blockIdx.x * 128 + t;                   // m = x*96 + y
    float sv[CC], q[CC];
    #pragma unroll
    for (int c = 0; c < CC; c++) sv[c] = g_s[c*NPIX + m];   // coalesced
    #pragma unroll
    for (int c = 0; c < CC; c++) q[c] = g_ut[c*NPIX + m];   // coalesced

    for (int cp = 0; cp < CC; cp++) {
        float v = sv[cp];
        #pragma unroll
        for (int c = 0; c < CC; c++) q[c] -= sA[c*CC + cp] * v;
    }

    if (last) {
        float* ob = out + m * CC;                   // out[(x*H+y)*C + c]
        #pragma unroll
        for (int c = 0; c < CC; c++) ob[c] = q[c];
    } else {
        float mx = q[0];
        #pragma unroll
        for (int c = 1; c < CC; c++) mx = fmaxf(mx, q[c]);
        float sum = 0.0f;
        float e[CC];
        #pragma unroll
        for (int c = 0; c < CC; c++) { e[c] = __expf(q[c] - mx); sum += e[c]; }
        float r = 1.0f / sum;
        #pragma unroll
        for (int c = 0; c < CC; c++) g_p[c*NPIX + m] = e[c] * r;
    }
}

extern "C" void kernel_launch(void* const* d_in, const int* in_sizes, int n_in,
                              void* d_out, int out_size) {
    const float* un = (const float*)d_in[0];
    // d_in[1] = rgb: provably unused (bilateral output replaced by spatial in source)
    const float* Ws = (const float*)d_in[2];
    const float* Wb = (const float*)d_in[3];
    const float* Cm = (const float*)d_in[4];
    float* out = (float*)d_out;

    init_kernel<<<56, 256>>>(un, Ws, Wb, Cm);
    for (int it = 0; it < NITER; it++) {
        blury_kernel<<<dim3(8, 21), 256>>>();
        blurx_kernel<<<dim3(6, 21), 256>>>();
        update_kernel<<<96, 128>>>(out, (it == NITER - 1) ? 1 : 0);
    }
}

// round 3
// speedup vs baseline: 1.8140x; 1.1370x over previous
#include <cuda_runtime.h>

#define HH 96
#define WW 128
#define CC 21
#define NPIX (HH*WW)   // 12288
#define NITER 5

// ---------------- scratch ----------------
__device__ float g_kx2[256];     // kprof(|j-127|), j=0..254
__device__ float g_ky2[192];     // kprof(|j-95|),  j=0..191
__device__ float g_rSx[WW];
__device__ float g_rSy[HH];
__device__ float g_A[CC*CC];     // compat @ (Ws + Wb)
__device__ float g_ut[CC*NPIX];  // unaries transposed  [c][x*96+y]
__device__ float g_r [CC*NPIX];  // r = A @ softmax(q)  [c][x*96+y]
__device__ float g_t1[CC*NPIX];  // after y-blur        [c][y*128+x]
__device__ float g_q [CC*NPIX];  // q = u - blur(r)*nrm [c][x*96+y]

// ============ init: tables + (softmax(u), r=A@p, ut) ============
// grid 200: blocks 0..191 pixel work (64 px x 4 subs); 192..199 tables+g_A.
__global__ void init_kernel(const float* __restrict__ un,
                            const float* __restrict__ Ws,
                            const float* __restrict__ Wb,
                            const float* __restrict__ Cm) {
    const float inv18 = 1.0f / 18.0f;
    if (blockIdx.x >= 192) {
        int idx = (blockIdx.x - 192) * 256 + threadIdx.x;
        int total = 255 + 192 + WW + HH + CC*CC;
        for (int i = idx; i < total; i += 8 * 256) {
            if (i < 255) {
                float d = fabsf((float)(i - 127));
                g_kx2[i] = expf(-d * d * inv18);
            } else if (i < 255 + 192) {
                float d = fabsf((float)((i - 255) - 95));
                g_ky2[i - 255] = expf(-d * d * inv18);
            } else if (i < 255 + 192 + WW) {
                int x = i - (255 + 192);
                float s = 0.0f;
                for (int xp = 0; xp < WW; xp++) {
                    float d = (float)(x - xp); s += expf(-d * d * inv18);
                }
                g_rSx[x] = 1.0f / s;
            } else if (i < 255 + 192 + WW + HH) {
                int y = i - (255 + 192 + WW);
                float s = 0.0f;
                for (int yp = 0; yp < HH; yp++) {
                    float d = (float)(y - yp); s += expf(-d * d * inv18);
                }
                g_rSy[y] = 1.0f / s;
            } else {
                int a = i - (255 + 192 + WW + HH);
                int rr = a / CC, cc = a % CC;
                float s = 0.0f;
                for (int k = 0; k < CC; k++)
                    s += Cm[rr*CC + k] * (Ws[k*CC + cc] + Wb[k*CC + cc]);
                g_A[a] = s;
            }
        }
        return;
    }
    // ---- pixel blocks: compute local A, then softmax + matvec ----
    __shared__ float sA[CC*CC];
    __shared__ float sp[64][22];
    int t = threadIdx.x;
    for (int a = t; a < CC*CC; a += 256) {      // recompute A locally (g_A not ready)
        int rr = a / CC, cc = a % CC;
        float s = 0.0f;
        for (int k = 0; k < CC; k++)
            s += Cm[rr*CC + k] * (Ws[k*CC + cc] + Wb[k*CC + cc]);
        sA[a] = s;
    }
    __syncthreads();

    int px = t >> 2, sub = t & 3;
    int m = blockIdx.x * 64 + px;               // m = x*96 + y
    int y = m % HH, x = m / HH;
    const float* ub = un + (y * WW + x) * CC;
    int cbase = sub * 5;
    int nc = (sub == 3) ? 6 : 5;

    float v[6]; float mx = -1e30f;
    #pragma unroll
    for (int k = 0; k < 6; k++) {
        if (k < nc) { v[k] = ub[cbase + k]; mx = fmaxf(mx, v[k]);
                      g_ut[(cbase + k)*NPIX + m] = v[k]; }
    }
    mx = fmaxf(mx, __shfl_xor_sync(0xffffffffu, mx, 1));
    mx = fmaxf(mx, __shfl_xor_sync(0xffffffffu, mx, 2));
    float sum = 0.0f;
    #pragma unroll
    for (int k = 0; k < 6; k++)
        if (k < nc) { v[k] = __expf(v[k] - mx); sum += v[k]; }
    sum += __shfl_xor_sync(0xffffffffu, sum, 1);
    sum += __shfl_xor_sync(0xffffffffu, sum, 2);
    float rinv = 1.0f / sum;
    #pragma unroll
    for (int k = 0; k < 6; k++)
        if (k < nc) sp[px][cbase + k] = v[k] * rinv;
    __syncwarp();

    #pragma unroll
    for (int k = 0; k < 6; k++) {
        if (k < nc) {
            int c = cbase + k;
            float acc = 0.0f;
            #pragma unroll
            for (int cp = 0; cp < CC; cp++) acc += sA[c*CC + cp] * sp[px][cp];
            g_r[c*NPIX + m] = acc;
        }
    }
}

// ============ y-blur: t1[c][y][x] = sum_yp r[c][x][yp] * ky ============
__global__ void blury_kernel() {
    __shared__ float sky[192];
    __shared__ float sp[16 * 97];
    int tid = threadIdx.x;
    int c  = blockIdx.y;
    int x0 = blockIdx.x * 16;
    if (tid < 192) sky[tid] = g_ky2[tid];
    const float* pc = g_r + c*NPIX + x0*96;
    #pragma unroll
    for (int i = tid; i < 16 * 24; i += 256) {
        int col = i / 24, j = i % 24;
        float4 v = *(const float4*)(pc + col*96 + j*4);
        float* d = &sp[col*97 + j*4];
        d[0] = v.x; d[1] = v.y; d[2] = v.z; d[3] = v.w;
    }
    __syncthreads();

    int lx = tid & 15, ty = tid >> 4;
    int y0 = ty * 6;
    const float* spv  = &sp[lx * 97];
    const float* skyb = &sky[95 - y0];
    float acc[6] = {0.f,0.f,0.f,0.f,0.f,0.f};
    float w[6];
    #pragma unroll
    for (int k = 0; k < 6; k++) w[k] = skyb[-k];
    #pragma unroll
    for (int yp = 0; yp < 96; yp++) {
        float v = spv[yp];
        #pragma unroll
        for (int k = 0; k < 6; k++) acc[k] += v * w[k];
        #pragma unroll
        for (int k = 5; k > 0; k--) w[k] = w[k-1];
        w[0] = skyb[yp + 1];
    }
    float* tb = g_t1 + c*NPIX + y0*128 + x0 + lx;
    #pragma unroll
    for (int k = 0; k < 6; k++) tb[k * 128] = acc[k];
}

// ============ x-blur + norm + update: q[c][x][y] = ut - blur*rSx*rSy ============
__global__ void blurx_kernel() {
    __shared__ float st[16 * 129];
    __shared__ float sw[16 * 137];
    __shared__ float ss[128 * 17];
    int tid = threadIdx.x;
    int c   = blockIdx.y;
    int y0b = blockIdx.x * 16;

    const float* tc = g_t1 + c*NPIX + y0b*128;
    #pragma unroll
    for (int i = tid; i < 16 * 32; i += 256) {
        int r = i >> 5, j = i & 31;
        float4 v = *(const float4*)(tc + r*128 + j*4);
        float* d = &st[r*129 + j*4];
        d[0] = v.x; d[1] = v.y; d[2] = v.z; d[3] = v.w;
    }
    for (int i = tid; i < 16 * 137; i += 256) {
        int xt = i / 137, mm = i % 137;
        int idx = mm + 120 - 8 * xt;
        sw[i] = g_kx2[idx > 254 ? 254 : idx];
    }
    __syncthreads();

    int xt = tid & 15, r = tid >> 4;
    const float* stv = &st[r * 129];
    const float* swt = &sw[xt * 137];
    float acc[8] = {0.f,0.f,0.f,0.f,0.f,0.f,0.f,0.f};
    float w[8];
    #pragma unroll
    for (int k = 0; k < 8; k++) w[k] = swt[7 - k];
    #pragma unroll
    for (int xp = 0; xp < 128; xp++) {
        float v = stv[xp];
        #pragma unroll
        for (int k = 0; k < 8; k++) acc[k] += v * w[k];
        #pragma unroll
        for (int k = 7; k > 0; k--) w[k] = w[k-1];
        w[0] = swt[xp + 8];
    }

    int x0 = xt * 8;
    float rn_y = g_rSy[y0b + r];
    #pragma unroll
    for (int k = 0; k < 8; k++)
        ss[(x0 + k) * 17 + r] = acc[k] * g_rSx[x0 + k] * rn_y;
    __syncthreads();

    // writeback: q = ut - s (coalesced float4 both sides)
    const float* utb = g_ut + c*NPIX + y0b;
    float*       qb  = g_q  + c*NPIX + y0b;
    #pragma unroll
    for (int i = tid; i < 512; i += 256) {
        int x = i >> 2, qq = i & 3;
        const float* p4 = &ss[x * 17 + qq * 4];
        float4 u4 = *(const float4*)(utb + x*96 + qq*4);
        float4 v = make_float4(u4.x - p4[0], u4.y - p4[1],
                               u4.z - p4[2], u4.w - p4[3]);
        *(float4*)(qb + x*96 + qq*4) = v;
    }
}

// ============ pix: p = softmax(q); r = A @ p  (4 threads/pixel) ============
__global__ void pix_kernel() {
    __shared__ float sA[CC*CC];
    __shared__ float sp[64][22];
    int t = threadIdx.x;
    for (int a = t; a < CC*CC; a += 256) sA[a] = g_A[a];
    __syncthreads();

    int px = t >> 2, sub = t & 3;
    int m = blockIdx.x * 64 + px;
    int cbase = sub * 5;
    int nc = (sub == 3) ? 6 : 5;

    float v[6]; float mx = -1e30f;
    #pragma unroll
    for (int k = 0; k < 6; k++)
        if (k < nc) { v[k] = g_q[(cbase + k)*NPIX + m]; mx = fmaxf(mx, v[k]); }
    mx = fmaxf(mx, __shfl_xor_sync(0xffffffffu, mx, 1));
    mx = fmaxf(mx, __shfl_xor_sync(0xffffffffu, mx, 2));
    float sum = 0.0f;
    #pragma unroll
    for (int k = 0; k < 6; k++)
        if (k < nc) { v[k] = __expf(v[k] - mx); sum += v[k]; }
    sum += __shfl_xor_sync(0xffffffffu, sum, 1);
    sum += __shfl_xor_sync(0xffffffffu, sum, 2);
    float rinv = 1.0f / sum;
    #pragma unroll
    for (int k = 0; k < 6; k++)
        if (k < nc) sp[px][cbase + k] = v[k] * rinv;
    __syncwarp();

    #pragma unroll
    for (int k = 0; k < 6; k++) {
        if (k < nc) {
            int c = cbase + k;
            float acc = 0.0f;
            #pragma unroll
            for (int cp = 0; cp < CC; cp++) acc += sA[c*CC + cp] * sp[px][cp];
            g_r[c*NPIX + m] = acc;
        }
    }
}

// ============ emit: transpose q -> out[(x*H+y)*C + c], coalesced ============
__global__ void emit_kernel(float* __restrict__ out) {
    __shared__ float sq[128 * 21];
    int t = threadIdx.x;
    int m0 = blockIdx.x * 128;
    for (int i = t; i < 128 * 21; i += 256) {
        int c = i >> 7, pp = i & 127;
        sq[pp * 21 + c] = g_q[c*NPIX + m0 + pp];    // coalesced rows
    }
    __syncthreads();
    float* ob = out + m0 * 21;
    for (int i = t; i < 128 * 21; i += 256) ob[i] = sq[i];  // contiguous
}

extern "C" void kernel_launch(void* const* d_in, const int* in_sizes, int n_in,
                              void* d_out, int out_size) {
    const float* un = (const float*)d_in[0];
    // d_in[1] = rgb: provably unused (bilateral term replaced by spatial in source)
    const float* Ws = (const float*)d_in[2];
    const float* Wb = (const float*)d_in[3];
    const float* Cm = (const float*)d_in[4];
    float* out = (float*)d_out;

    init_kernel<<<200, 256>>>(un, Ws, Wb, Cm);
    for (int it = 0; it < NITER; it++) {
        blury_kernel<<<dim3(8, 21), 256>>>();
        blurx_kernel<<<dim3(6, 21), 256>>>();
        if (it < NITER - 1) pix_kernel<<<192, 256>>>();
    }
    emit_kernel<<<96, 256>>>(out);
}

// round 5
// speedup vs baseline: 2.3267x; 1.2826x over previous
#include <cuda_runtime.h>

#define HH 96
#define WW 128
#define CC 21
#define NPIX (HH*WW)   // 12288
#define NITER 5

// ---------------- scratch ----------------
__device__ float g_kt[48];       // truncated profile: exp(-(j-24)^2/18) if |j-24|<=16 else 0
__device__ float g_rSx[WW];      // full-kernel normalizers (exact, like reference)
__device__ float g_rSy[HH];
__device__ float g_A[CC*CC];     // compat @ (Ws + Wb)
__device__ float g_ut[CC*NPIX];  // unaries transposed  [c][x*96+y]
__device__ float g_r [CC*NPIX];  // r = A @ softmax(q)  [c][x*96+y]
__device__ float g_t1[CC*NPIX];  // after y-blur        [c][y*128+x]
__device__ float g_q [CC*NPIX];  // q = u - blur(r)*nrm [c][x*96+y]

// ======== init: tables + (softmax(u), ut, r=A@p) — 8 subs/pixel ========
// grid 392: blocks 0..383 pixel work (32 px x 8 subs); 384..391 tables.
__global__ void init_kernel(const float* __restrict__ un,
                            const float* __restrict__ Ws,
                            const float* __restrict__ Wb,
                            const float* __restrict__ Cm) {
    const float inv18 = 1.0f / 18.0f;
    if (blockIdx.x >= 384) {
        int idx = (blockIdx.x - 384) * 256 + threadIdx.x;
        int total = 48 + WW + HH + CC*CC;           // 713
        if (idx < total) {
            int i = idx;
            if (i < 48) {
                float d = fabsf((float)(i - 24));
                g_kt[i] = (d <= 16.0f) ? expf(-d * d * inv18) : 0.0f;
            } else if (i < 48 + WW) {
                int x = i - 48;
                float s = 0.0f;
                for (int xp = 0; xp < WW; xp++) {
                    float d = (float)(x - xp); s += expf(-d * d * inv18);
                }
                g_rSx[x] = 1.0f / s;
            } else if (i < 48 + WW + HH) {
                int y = i - (48 + WW);
                float s = 0.0f;
                for (int yp = 0; yp < HH; yp++) {
                    float d = (float)(y - yp); s += expf(-d * d * inv18);
                }
                g_rSy[y] = 1.0f / s;
            } else {
                int a = i - (48 + WW + HH);
                int rr = a / CC, cc = a % CC;
                float s = 0.0f;
                for (int k = 0; k < CC; k++)
                    s += Cm[rr*CC + k] * (Ws[k*CC + cc] + Wb[k*CC + cc]);
                g_A[a] = s;
            }
        }
        return;
    }
    __shared__ float sA[CC*CC];
    __shared__ float sp[32][22];
    int t = threadIdx.x;
    for (int a = t; a < CC*CC; a += 256) {          // local A (g_A not ready yet)
        int rr = a / CC, cc = a % CC;
        float s = 0.0f;
        for (int k = 0; k < CC; k++)
            s += Cm[rr*CC + k] * (Ws[k*CC + cc] + Wb[k*CC + cc]);
        sA[a] = s;
    }
    __syncthreads();

    int px = t >> 3, sub = t & 7;
    int m = blockIdx.x * 32 + px;                   // m = x*96 + y
    int y = m % HH, x = m / HH;
    const float* ub = un + (y * WW + x) * CC;
    int nc    = (sub < 5) ? 3 : 2;
    int cbase = (sub < 5) ? 3*sub : 2*sub + 5;

    float v[3]; float mx = -1e30f;
    #pragma unroll
    for (int k = 0; k < 3; k++)
        if (k < nc) { v[k] = ub[cbase + k]; mx = fmaxf(mx, v[k]);
                      g_ut[(cbase + k)*NPIX + m] = v[k]; }
    mx = fmaxf(mx, __shfl_xor_sync(0xffffffffu, mx, 1));
    mx = fmaxf(mx, __shfl_xor_sync(0xffffffffu, mx, 2));
    mx = fmaxf(mx, __shfl_xor_sync(0xffffffffu, mx, 4));
    float sum = 0.0f;
    #pragma unroll
    for (int k = 0; k < 3; k++)
        if (k < nc) { v[k] = __expf(v[k] - mx); sum += v[k]; }
    sum += __shfl_xor_sync(0xffffffffu, sum, 1);
    sum += __shfl_xor_sync(0xffffffffu, sum, 2);
    sum += __shfl_xor_sync(0xffffffffu, sum, 4);
    float rinv = 1.0f / sum;
    #pragma unroll
    for (int k = 0; k < 3; k++)
        if (k < nc) sp[px][cbase + k] = v[k] * rinv;
    __syncwarp();

    float acc[3] = {0.f, 0.f, 0.f};
    #pragma unroll
    for (int cp = 0; cp < CC; cp++) {
        float pv = sp[px][cp];
        #pragma unroll
        for (int k = 0; k < 3; k++) acc[k] += sA[(cbase + k)*CC + cp] * pv;
    }
    #pragma unroll
    for (int k = 0; k < 3; k++)
        if (k < nc) g_r[(cbase + k)*NPIX + m] = acc[k];
}

// ======== y-blur (radius 16): t1[c][y][x] = sum_yp r[c][x][yp]*k(|yp-y|) ========
// grid (8,21), block 256 = 16 cols x 16 rows; thread computes 6 y outputs.
__global__ void blury_kernel() {
    __shared__ float skt[64];
    __shared__ float sp[16 * 129];                  // [col][yp+16], zero-padded
    int tid = threadIdx.x;
    int c  = blockIdx.y;
    int x0 = blockIdx.x * 16;
    if (tid < 64) skt[tid] = (tid < 48) ? g_kt[tid] : 0.0f;
    #pragma unroll
    for (int i = tid; i < 512; i += 256) {          // zero pads [0,16) & [112,128)
        int col = i >> 5, off = i & 31;
        sp[col*129 + (off < 16 ? off : off + 96)] = 0.0f;
    }
    const float* pc = g_r + c*NPIX + x0*96;
    #pragma unroll
    for (int i = tid; i < 16 * 24; i += 256) {      // 16 cols x 24 float4
        int col = i / 24, j = i % 24;
        float4 v = *(const float4*)(pc + col*96 + j*4);
        float* d = &sp[col*129 + 16 + j*4];
        d[0] = v.x; d[1] = v.y; d[2] = v.z; d[3] = v.w;
    }
    __syncthreads();

    int lx = tid & 15, ty = tid >> 4;
    int y0 = ty * 6;
    const float* spv = &sp[lx * 129];
    float acc[6] = {0.f,0.f,0.f,0.f,0.f,0.f};
    float w[6];
    #pragma unroll
    for (int k = 0; k < 6; k++) w[k] = skt[8 - k];
    #pragma unroll
    for (int j = 8; j < 46; j++) {                  // 38 taps
        float v = spv[y0 + j - 8];
        #pragma unroll
        for (int k = 0; k < 6; k++) acc[k] += v * w[k];
        #pragma unroll
        for (int k = 5; k > 0; k--) w[k] = w[k-1];
        w[0] = skt[j + 1];
    }
    float* tb = g_t1 + c*NPIX + y0*128 + x0 + lx;
    #pragma unroll
    for (int k = 0; k < 6; k++) tb[k * 128] = acc[k];
}

// ======== x-blur (radius 16) + norm + update; last iter emits NHWC out ========
// grid (6,21), block 256 = 16 x-tiles x 16 rows; thread computes 8 x outputs.
__global__ void blurx_kernel(float* __restrict__ out, int last) {
    __shared__ float skt[64];
    __shared__ float st[16 * 161];                  // [row][xp+16], zero-padded
    __shared__ float ss[128 * 17];                  // staged transpose [x][row]
    int tid = threadIdx.x;
    int c   = blockIdx.y;
    int y0b = blockIdx.x * 16;
    if (tid < 64) skt[tid] = (tid < 48) ? g_kt[tid] : 0.0f;
    #pragma unroll
    for (int i = tid; i < 512; i += 256) {          // zero pads [0,16) & [144,160)
        int r = i >> 5, off = i & 31;
        st[r*161 + (off < 16 ? off : off + 128)] = 0.0f;
    }
    const float* tc = g_t1 + c*NPIX + y0b*128;
    #pragma unroll
    for (int i = tid; i < 16 * 32; i += 256) {      // 16 rows x 32 float4
        int r = i >> 5, j = i & 31;
        float4 v = *(const float4*)(tc + r*128 + j*4);
        float* d = &st[r*161 + 16 + j*4];
        d[0] = v.x; d[1] = v.y; d[2] = v.z; d[3] = v.w;
    }
    __syncthreads();

    int xt = tid & 15, r = tid >> 4;
    int x0 = xt * 8;
    const float* stv = &st[r * 161];
    float acc[8] = {0.f,0.f,0.f,0.f,0.f,0.f,0.f,0.f};
    float w[8];
    #pragma unroll
    for (int k = 0; k < 8; k++) w[k] = skt[8 - k];
    #pragma unroll
    for (int j = 8; j < 48; j++) {                  // 40 taps
        float v = stv[x0 + j - 8];
        #pragma unroll
        for (int k = 0; k < 8; k++) acc[k] += v * w[k];
        #pragma unroll
        for (int k = 7; k > 0; k--) w[k] = w[k-1];
        w[0] = skt[j + 1];
    }

    float rn_y = g_rSy[y0b + r];
    #pragma unroll
    for (int k = 0; k < 8; k++)
        ss[(x0 + k) * 17 + r] = acc[k] * g_rSx[x0 + k] * rn_y;
    __syncthreads();

    if (last) {
        // q = ut - s, emitted directly to out[(x*96+y)*21 + c]
        const float* utb = g_ut + c*NPIX + y0b;
        for (int i = tid; i < 2048; i += 256) {
            int x = i >> 4, yy = i & 15;
            float u = utb[x*96 + yy];
            out[(x*HH + y0b + yy)*CC + c] = u - ss[x*17 + yy];
        }
    } else {
        const float* utb = g_ut + c*NPIX + y0b;
        float*       qb  = g_q  + c*NPIX + y0b;
        #pragma unroll
        for (int i = tid; i < 512; i += 256) {
            int x = i >> 2, qq = i & 3;
            const float* p4 = &ss[x * 17 + qq * 4];
            float4 u4 = *(const float4*)(utb + x*96 + qq*4);
            float4 v = make_float4(u4.x - p4[0], u4.y - p4[1],
                                   u4.z - p4[2], u4.w - p4[3]);
            *(float4*)(qb + x*96 + qq*4) = v;
        }
    }
}

// ======== pix: p = softmax(q); r = A @ p  (8 threads/pixel) ========
__global__ void pix_kernel() {
    __shared__ float sA[CC*CC];
    __shared__ float sp[32][22];
    int t = threadIdx.x;
    for (int a = t; a < CC*CC; a += 256) sA[a] = g_A[a];
    __syncthreads();

    int px = t >> 3, sub = t & 7;
    int m = blockIdx.x * 32 + px;
    int nc    = (sub < 5) ? 3 : 2;
    int cbase = (sub < 5) ? 3*sub : 2*sub + 5;

    float v[3]; float mx = -1e30f;
    #pragma unroll
    for (int k = 0; k < 3; k++)
        if (k < nc) { v[k] = g_q[(cbase + k)*NPIX + m]; mx = fmaxf(mx, v[k]); }
    mx = fmaxf(mx, __shfl_xor_sync(0xffffffffu, mx, 1));
    mx = fmaxf(mx, __shfl_xor_sync(0xffffffffu, mx, 2));
    mx = fmaxf(mx, __shfl_xor_sync(0xffffffffu, mx, 4));
    float sum = 0.0f;
    #pragma unroll
    for (int k = 0; k < 3; k++)
        if (k < nc) { v[k] = __expf(v[k] - mx); sum += v[k]; }
    sum += __shfl_xor_sync(0xffffffffu, sum, 1);
    sum += __shfl_xor_sync(0xffffffffu, sum, 2);
    sum += __shfl_xor_sync(0xffffffffu, sum, 4);
    float rinv = 1.0f / sum;
    #pragma unroll
    for (int k = 0; k < 3; k++)
        if (k < nc) sp[px][cbase + k] = v[k] * rinv;
    __syncwarp();

    float acc[3] = {0.f, 0.f, 0.f};
    #pragma unroll
    for (int cp = 0; cp < CC; cp++) {
        float pv = sp[px][cp];
        #pragma unroll
        for (int k = 0; k < 3; k++) acc[k] += sA[(cbase + k)*CC + cp] * pv;
    }
    #pragma unroll
    for (int k = 0; k < 3; k++)
        if (k < nc) g_r[(cbase + k)*NPIX + m] = acc[k];
}

extern "C" void kernel_launch(void* const* d_in, const int* in_sizes, int n_in,
                              void* d_out, int out_size) {
    const float* un = (const float*)d_in[0];
    // d_in[1] = rgb: provably unused (bilateral term replaced by spatial in source)
    const float* Ws = (const float*)d_in[2];
    const float* Wb = (const float*)d_in[3];
    const float* Cm = (const float*)d_in[4];
    float* out = (float*)d_out;

    init_kernel<<<392, 256>>>(un, Ws, Wb, Cm);
    for (int it = 0; it < NITER; it++) {
        blury_kernel<<<dim3(8, 21), 256>>>();
        blurx_kernel<<<dim3(6, 21), 256>>>(out, (it == NITER - 1) ? 1 : 0);
        if (it < NITER - 1) pix_kernel<<<384, 256>>>();
    }
}